// round 10
// baseline (speedup 1.0000x reference)
#include <cuda_runtime.h>
#include <cuda_fp16.h>
#include <cstdint>

// STN flow-relative bilinear warp, two-pass with fp16 NHWC scratch:
//   pass 1: NCHW f32 -> channel-PERMUTED NHWC fp16 scratch
//           (scratch position q holds channel 4*(q&7) + (q>>3))
//   pass 2: cooperative gather (4 lanes/pixel, 2 pixels/thread, MLP=8);
//           output via cp.async.bulk in TWO 16-channel rounds through a
//           small 8.7KB stage buffer -> high occupancy + stores off L1 pipe.

static constexpr int H  = 1024;
static constexpr int W  = 1024;
static constexpr int C  = 32;
static constexpr int HW = H * W;

static constexpr int STG_STRIDE = 136;   // floats; 544B rows, 16B-aligned

// 64 MB scratch: x transposed to [H*W][32] fp16, channels permuted
__device__ __half g_xt[(size_t)HW * C];

__device__ __forceinline__ uint32_t smem_u32(const void* p) {
    return (uint32_t)__cvta_generic_to_shared(p);
}

// ---------------- pass 1: NCHW -> permuted NHWC fp16 ----------------
__device__ __forceinline__ int sw_addr(int c, int px) {
    return c * 128 + 4 * ((px >> 2) ^ (c >> 2)) + (px & 3);
}

__global__ __launch_bounds__(256) void transpose_kernel(const float* __restrict__ x)
{
    __shared__ float s[32 * 128];

    int tid = threadIdx.x;
    int p0  = blockIdx.x * 128;

#pragma unroll
    for (int i = 0; i < 4; ++i) {
        int j   = i * 256 + tid;
        int c   = j >> 5;
        int pxg = j & 31;
        float4 v = __ldcs((const float4*)(x + (size_t)c * HW + p0 + 4 * pxg));
        *(float4*)(s + c * 128 + 4 * (pxg ^ (c >> 2))) = v;
    }
    __syncthreads();

#pragma unroll
    for (int i = 0; i < 4; ++i) {
        int j  = i * 256 + tid;
        int pl = j >> 3;
        int cg = j & 7;            // position group: positions 4cg..4cg+3
        // position q holds channel 4*(q&7) + (q>>3)
        int q0 = 4 * cg;
        int c0 = 4 * ((q0 + 0) & 7) + ((q0 + 0) >> 3);
        int c1 = 4 * ((q0 + 1) & 7) + ((q0 + 1) >> 3);
        int c2 = 4 * ((q0 + 2) & 7) + ((q0 + 2) >> 3);
        int c3 = 4 * ((q0 + 3) & 7) + ((q0 + 3) >> 3);
        __half2 h0 = __floats2half2_rn(s[sw_addr(c0, pl)], s[sw_addr(c1, pl)]);
        __half2 h1 = __floats2half2_rn(s[sw_addr(c2, pl)], s[sw_addr(c3, pl)]);
        uint2 v;
        v.x = *(const unsigned int*)&h0;
        v.y = *(const unsigned int*)&h1;
        *(uint2*)(g_xt + (size_t)(p0 + pl) * C + 4 * cg) = v;
    }
}

// ---------------- pass 2: bilinear warp from fp16 NHWC ----------------
__global__ __launch_bounds__(256, 6) void warp_bilinear_coop_kernel(
    const float* __restrict__ flow,
    float* __restrict__ out)
{
    __shared__ int   s_off[4][128];
    __shared__ float s_w[4][128];
    __shared__ float s_stage[16 * STG_STRIDE];   // 16 channel rows x 128 px

    int tid = threadIdx.x;
    int p0  = blockIdx.x * 128;

    if (tid < 128) {
        int p  = p0 + tid;
        int px = p & (W - 1);
        int py = p >> 10;              // W == 1024

        float fx = flow[p];
        float fy = flow[HW + p];

        // Match reference math exactly (normalize + unnormalize round-trip)
        float gx = (fx + (float)px) * (2.0f / (float)(W - 1)) - 1.0f;
        float gy = (fy + (float)py) * (2.0f / (float)(H - 1)) - 1.0f;
        float ix = ((gx + 1.0f) * (float)W - 1.0f) * 0.5f;
        float iy = ((gy + 1.0f) * (float)H - 1.0f) * 0.5f;

        float x0f = floorf(ix);
        float y0f = floorf(iy);
        float wx1 = ix - x0f;
        float wy1 = iy - y0f;
        float wx0 = 1.0f - wx1;
        float wy0 = 1.0f - wy1;

        int x0 = (int)x0f;
        int y0 = (int)y0f;
        int x1 = x0 + 1;
        int y1 = y0 + 1;

        float vx0 = (x0 >= 0 && x0 < W) ? 1.0f : 0.0f;
        float vx1 = (x1 >= 0 && x1 < W) ? 1.0f : 0.0f;
        float vy0 = (y0 >= 0 && y0 < H) ? 1.0f : 0.0f;
        float vy1 = (y1 >= 0 && y1 < H) ? 1.0f : 0.0f;

        int cx0 = min(max(x0, 0), W - 1);
        int cx1 = min(max(x1, 0), W - 1);
        int cy0 = min(max(y0, 0), H - 1);
        int cy1 = min(max(y1, 0), H - 1);

        s_w[0][tid] = wx0 * wy0 * vx0 * vy0;
        s_w[1][tid] = wx1 * wy0 * vx1 * vy0;
        s_w[2][tid] = wx0 * wy1 * vx0 * vy1;
        s_w[3][tid] = wx1 * wy1 * vx1 * vy1;

        s_off[0][tid] = cy0 * W + cx0;
        s_off[1][tid] = cy0 * W + cx1;
        s_off[2][tid] = cy1 * W + cx0;
        s_off[3][tid] = cy1 * W + cx1;
    }
    __syncthreads();

    int pl = tid >> 2;                 // 0..63 -> pixels pl and pl+64
    int cg = tid & 3;                  // position octet (0..3)

    // hoist smem reads, front-batch ALL 8 corner loads (MLP=8)
    int   off[2][4];
    float wgt[2][4];
#pragma unroll
    for (int half = 0; half < 2; ++half) {
        int pp = pl + half * 64;
#pragma unroll
        for (int k = 0; k < 4; ++k) {
            off[half][k] = s_off[k][pp];
            wgt[half][k] = s_w[k][pp];
        }
    }

    uint4 v[2][4];
#pragma unroll
    for (int half = 0; half < 2; ++half)
#pragma unroll
        for (int k = 0; k < 4; ++k)
            v[half][k] = __ldg((const uint4*)(g_xt + (size_t)off[half][k] * C) + cg);

    // ---- round A: channels 0..15 (positions .x/.y of each uint4) ----
#pragma unroll
    for (int half = 0; half < 2; ++half) {
        int pp = pl + half * 64;
        float a[4] = {0.f, 0.f, 0.f, 0.f};
#pragma unroll
        for (int k = 0; k < 4; ++k) {
            float w = wgt[half][k];
            float2 f0 = __half22float2(*(const __half2*)&v[half][k].x);
            float2 f1 = __half22float2(*(const __half2*)&v[half][k].y);
            a[0] += w * f0.x;  a[1] += w * f0.y;
            a[2] += w * f1.x;  a[3] += w * f1.y;
        }
        // position 8cg+j holds channel 4j+cg (j=0..3 here): row 4j+cg
#pragma unroll
        for (int j = 0; j < 4; ++j)
            s_stage[(4 * j + cg) * STG_STRIDE + pp] = a[j];
    }
    __syncthreads();

    if (tid < 16) {
        asm volatile("fence.proxy.async.shared::cta;" ::: "memory");
        uint32_t src = smem_u32(s_stage + tid * STG_STRIDE);
        float*   dst = out + (size_t)tid * HW + p0;
        asm volatile(
            "cp.async.bulk.global.shared::cta.bulk_group [%0], [%1], %2;"
            :: "l"(dst), "r"(src), "r"(512) : "memory");
        asm volatile("cp.async.bulk.commit_group;" ::: "memory");
        asm volatile("cp.async.bulk.wait_group 0;" ::: "memory");
    }
    __syncthreads();   // stage buffer free for reuse

    // ---- round B: channels 16..31 (positions .z/.w) ----
#pragma unroll
    for (int half = 0; half < 2; ++half) {
        int pp = pl + half * 64;
        float a[4] = {0.f, 0.f, 0.f, 0.f};
#pragma unroll
        for (int k = 0; k < 4; ++k) {
            float w = wgt[half][k];
            float2 f2 = __half22float2(*(const __half2*)&v[half][k].z);
            float2 f3 = __half22float2(*(const __half2*)&v[half][k].w);
            a[0] += w * f2.x;  a[1] += w * f2.y;
            a[2] += w * f3.x;  a[3] += w * f3.y;
        }
        // j=4..7: channel 4j+cg = 16 + (4(j-4)+cg): row (j-4)*4+cg in buffer
#pragma unroll
        for (int j = 0; j < 4; ++j)
            s_stage[(4 * j + cg) * STG_STRIDE + pp] = a[j];
    }
    __syncthreads();

    if (tid < 16) {
        asm volatile("fence.proxy.async.shared::cta;" ::: "memory");
        uint32_t src = smem_u32(s_stage + tid * STG_STRIDE);
        float*   dst = out + (size_t)(16 + tid) * HW + p0;
        asm volatile(
            "cp.async.bulk.global.shared::cta.bulk_group [%0], [%1], %2;"
            :: "l"(dst), "r"(src), "r"(512) : "memory");
        asm volatile("cp.async.bulk.commit_group;" ::: "memory");
        asm volatile("cp.async.bulk.wait_group 0;" ::: "memory");
    }
}

extern "C" void kernel_launch(void* const* d_in, const int* in_sizes, int n_in,
                              void* d_out, int out_size)
{
    const float* flow = (const float*)d_in[0];   // [1,2,H,W]
    const float* x    = (const float*)d_in[1];   // [1,C,H,W]
    float* out        = (float*)d_out;           // [1,C,H,W]

    (void)in_sizes; (void)n_in; (void)out_size;

    transpose_kernel<<<HW / 128, 256>>>(x);
    warp_bilinear_coop_kernel<<<HW / 128, 256>>>(flow, out);
}

// round 11
// speedup vs baseline: 1.4783x; 1.4783x over previous
#include <cuda_runtime.h>
#include <cuda_fp16.h>
#include <cstdint>

// STN flow-relative bilinear warp, two-pass with fp16 NHWC scratch:
//   pass 1: NCHW f32 -> NHWC fp16 scratch (swizzled smem transpose)
//   pass 2: cooperative gather (4 lanes/pixel, ADJACENT pixel pair per
//           thread, MLP=8) with direct float2 NCHW stores (half the store
//           instructions / line-touches of scalar stores).

static constexpr int H  = 1024;
static constexpr int W  = 1024;
static constexpr int C  = 32;
static constexpr int HW = H * W;

// 64 MB scratch: x transposed to [H*W][C] in fp16 (mostly L2-resident)
__device__ __half g_xt[(size_t)HW * C];

// ---------------- pass 1: NCHW -> NHWC transpose + f32->fp16 ----------------
__device__ __forceinline__ int sw_addr(int c, int px) {
    return c * 128 + 4 * ((px >> 2) ^ (c >> 2)) + (px & 3);
}

__global__ __launch_bounds__(256) void transpose_kernel(const float* __restrict__ x)
{
    __shared__ float s[32 * 128];

    int tid = threadIdx.x;
    int p0  = blockIdx.x * 128;

#pragma unroll
    for (int i = 0; i < 4; ++i) {
        int j   = i * 256 + tid;
        int c   = j >> 5;
        int pxg = j & 31;
        float4 v = __ldcs((const float4*)(x + (size_t)c * HW + p0 + 4 * pxg));
        *(float4*)(s + c * 128 + 4 * (pxg ^ (c >> 2))) = v;
    }
    __syncthreads();

#pragma unroll
    for (int i = 0; i < 4; ++i) {
        int j  = i * 256 + tid;
        int pl = j >> 3;
        int cg = j & 7;
        __half2 h0 = __floats2half2_rn(s[sw_addr(4 * cg + 0, pl)],
                                       s[sw_addr(4 * cg + 1, pl)]);
        __half2 h1 = __floats2half2_rn(s[sw_addr(4 * cg + 2, pl)],
                                       s[sw_addr(4 * cg + 3, pl)]);
        uint2 v;
        v.x = *(const unsigned int*)&h0;
        v.y = *(const unsigned int*)&h1;
        *(uint2*)(g_xt + (size_t)(p0 + pl) * C + 4 * cg) = v;
    }
}

// ---------------- pass 2: bilinear warp from fp16 NHWC ----------------
// Block = 256 threads, 128 pixels. Thread = (pixel-pair, channel-octet):
// pixels 2*pl and 2*pl+1 (adjacent) -> float2 stores.
__global__ __launch_bounds__(256) void warp_bilinear_coop_kernel(
    const float* __restrict__ flow,
    float* __restrict__ out)
{
    __shared__ int   s_off[4][128];
    __shared__ float s_w[4][128];

    int tid = threadIdx.x;
    int p0  = blockIdx.x * 128;

    if (tid < 128) {
        int p  = p0 + tid;
        int px = p & (W - 1);
        int py = p >> 10;              // W == 1024

        float fx = flow[p];
        float fy = flow[HW + p];

        // Match reference math exactly (normalize + unnormalize round-trip)
        float gx = (fx + (float)px) * (2.0f / (float)(W - 1)) - 1.0f;
        float gy = (fy + (float)py) * (2.0f / (float)(H - 1)) - 1.0f;
        float ix = ((gx + 1.0f) * (float)W - 1.0f) * 0.5f;
        float iy = ((gy + 1.0f) * (float)H - 1.0f) * 0.5f;

        float x0f = floorf(ix);
        float y0f = floorf(iy);
        float wx1 = ix - x0f;
        float wy1 = iy - y0f;
        float wx0 = 1.0f - wx1;
        float wy0 = 1.0f - wy1;

        int x0 = (int)x0f;
        int y0 = (int)y0f;
        int x1 = x0 + 1;
        int y1 = y0 + 1;

        float vx0 = (x0 >= 0 && x0 < W) ? 1.0f : 0.0f;
        float vx1 = (x1 >= 0 && x1 < W) ? 1.0f : 0.0f;
        float vy0 = (y0 >= 0 && y0 < H) ? 1.0f : 0.0f;
        float vy1 = (y1 >= 0 && y1 < H) ? 1.0f : 0.0f;

        int cx0 = min(max(x0, 0), W - 1);
        int cx1 = min(max(x1, 0), W - 1);
        int cy0 = min(max(y0, 0), H - 1);
        int cy1 = min(max(y1, 0), H - 1);

        s_w[0][tid] = wx0 * wy0 * vx0 * vy0;
        s_w[1][tid] = wx1 * wy0 * vx1 * vy0;
        s_w[2][tid] = wx0 * wy1 * vx0 * vy1;
        s_w[3][tid] = wx1 * wy1 * vx1 * vy1;

        s_off[0][tid] = cy0 * W + cx0;
        s_off[1][tid] = cy0 * W + cx1;
        s_off[2][tid] = cy1 * W + cx0;
        s_off[3][tid] = cy1 * W + cx1;
    }
    __syncthreads();

    int pl = tid >> 2;                 // 0..63 -> pixels 2*pl, 2*pl+1
    int cg = tid & 3;                  // channel octet (0..3), 8 halves each

    // hoist all smem reads, then front-batch ALL 8 corner loads (MLP=8)
    int   off[2][4];
    float wgt[2][4];
#pragma unroll
    for (int half = 0; half < 2; ++half) {
        int pp = 2 * pl + half;
#pragma unroll
        for (int k = 0; k < 4; ++k) {
            off[half][k] = s_off[k][pp];
            wgt[half][k] = s_w[k][pp];
        }
    }

    uint4 v[2][4];
#pragma unroll
    for (int half = 0; half < 2; ++half)
#pragma unroll
        for (int k = 0; k < 4; ++k)
            v[half][k] = __ldg((const uint4*)(g_xt + (size_t)off[half][k] * C) + cg);

    float a[2][8];
#pragma unroll
    for (int half = 0; half < 2; ++half) {
#pragma unroll
        for (int j = 0; j < 8; ++j) a[half][j] = 0.f;
#pragma unroll
        for (int k = 0; k < 4; ++k) {
            float w = wgt[half][k];
            float2 f0 = __half22float2(*(const __half2*)&v[half][k].x);
            float2 f1 = __half22float2(*(const __half2*)&v[half][k].y);
            float2 f2 = __half22float2(*(const __half2*)&v[half][k].z);
            float2 f3 = __half22float2(*(const __half2*)&v[half][k].w);
            a[half][0] += w * f0.x;  a[half][1] += w * f0.y;
            a[half][2] += w * f1.x;  a[half][3] += w * f1.y;
            a[half][4] += w * f2.x;  a[half][5] += w * f2.y;
            a[half][6] += w * f3.x;  a[half][7] += w * f3.y;
        }
    }

    // float2 NCHW stores: channel 8*cg+j, adjacent pixel pair 2*pl..2*pl+1.
    // Per warp-inst: 4 channel planes x 8 lanes x 8B = 4 contiguous 64B runs.
    float* ob = out + (size_t)(cg * 8) * HW + p0 + 2 * pl;
#pragma unroll
    for (int j = 0; j < 8; ++j) {
        float2 st = make_float2(a[0][j], a[1][j]);
        __stcs((float2*)(ob + (size_t)j * HW), st);
    }
}

extern "C" void kernel_launch(void* const* d_in, const int* in_sizes, int n_in,
                              void* d_out, int out_size)
{
    const float* flow = (const float*)d_in[0];   // [1,2,H,W]
    const float* x    = (const float*)d_in[1];   // [1,C,H,W]
    float* out        = (float*)d_out;           // [1,C,H,W]

    (void)in_sizes; (void)n_in; (void)out_size;

    transpose_kernel<<<HW / 128, 256>>>(x);
    warp_bilinear_coop_kernel<<<HW / 128, 256>>>(flow, out);
}